// round 11
// baseline (speedup 1.0000x reference)
#include <cuda_runtime.h>
#include <cuda_bf16.h>

#define SIDE 9
#define STATE 81
#define NA 5
#define H 32
#define WARPS_K1 8
#define K2_THREADS 256
#define K2_ROWS 256
#define NCHUNK 8

// ---------------------------------------------------------------------------
// K1: warp-per-row scatter + reward (round-3 proven form + chunk offset).
// ---------------------------------------------------------------------------
__global__ __launch_bounds__(32 * WARPS_K1) void k1_nsc_reward(
    const float* __restrict__ obs,          // (B, 3*STATE)
    const float* __restrict__ acr_g,        // (B, STATE*NA)
    float* __restrict__ out,                // [sym(B), imm(B), ret(B), nsc(B*81)]
    int B, int row0, int nrows)
{
    __shared__ float s[WARPS_K1][416];

    const int wid  = threadIdx.x >> 5;
    const int lane = threadIdx.x & 31;
    const long long row = (long long)row0 + (long long)blockIdx.x * WARPS_K1 + wid;
    if (row >= (long long)row0 + nrows) return;

    const float* __restrict__ acr = acr_g + row * (STATE * NA);
    float* __restrict__ sp = s[wid];
    #pragma unroll
    for (int k = 0; k < 13; k++) {
        const int i = lane + 32 * k;
        if (i < STATE * NA) sp[i] = __ldg(&acr[i]);
    }
    __syncwarp();

    const float* __restrict__ dem = obs + row * (3 * STATE) + 2 * STATE;
    float* __restrict__ nout = out + 3LL * B + row * STATE;

    float imm = 0.0f;
    #pragma unroll
    for (int k = 0; k < 3; k++) {
        const int c = lane + 32 * k;
        if (c < STATE) {
            const int r   = c / SIDE;
            const int col = c - r * SIDE;
            float v = sp[c * NA + 0];
            if (r == 0)        v += sp[c * NA + 1];
            if (r < SIDE - 1)  v += sp[(c + SIDE) * NA + 1];
            if (r == SIDE - 1) v += sp[c * NA + 2];
            if (r > 0)         v += sp[(c - SIDE) * NA + 2];
            if (col == 0)      v += sp[c * NA + 3];
            if (col < SIDE - 1)v += sp[(c + 1) * NA + 3];
            if (col == SIDE-1) v += sp[c * NA + 4];
            if (col > 0)       v += sp[(c - 1) * NA + 4];

            nout[c] = v;
            imm += fminf(v, __ldg(&dem[c]));
        }
    }

    #pragma unroll
    for (int o = 16; o; o >>= 1) imm += __shfl_xor_sync(0xffffffffu, imm, o);
    if (lane == 0) out[(long long)B + row] = imm;
}

// ---------------------------------------------------------------------------
// Packed f32x2 helpers (sm_103a FFMA2)
// ---------------------------------------------------------------------------
__device__ __forceinline__ unsigned long long pack2(float x) {
    unsigned long long r;
    asm("mov.b64 %0, {%1, %1};" : "=l"(r) : "f"(x));
    return r;
}
__device__ __forceinline__ void ffma2(unsigned long long& d,
                                      unsigned long long a,
                                      unsigned long long b) {
    asm("fma.rn.f32x2 %0, %1, %2, %0;" : "+l"(d) : "l"(a), "l"(b));
}
__device__ __forceinline__ void unpack2(unsigned long long p, float& lo, float& hi) {
    asm("mov.b64 {%0, %1}, %2;" : "=f"(lo), "=f"(hi) : "l"(p));
}

// ---------------------------------------------------------------------------
// K2: round-3 proven form (thread-per-row, smem-staged nsc) + chunk offset.
// Runs on a second stream, overlapped under K1's DRAM stalls; nsc is L2-hot.
// ---------------------------------------------------------------------------
__global__ __launch_bounds__(K2_THREADS) void k2_mlp(
    const float* __restrict__ W1,
    const float* __restrict__ W2,
    const float* __restrict__ W3,
    const float* __restrict__ b3,
    float* __restrict__ out,
    int B, int row0, int nrows)
{
    extern __shared__ float smem[];
    float* s_nsc = smem;                          // K2_ROWS * STATE
    float* sW1   = s_nsc + K2_ROWS * STATE;       // STATE * H
    float* sW2   = sW1 + STATE * H;               // H * H
    float* sW3   = sW2 + H * H;                   // H
    float* sb3   = sW3 + H;                       // 1

    for (int i = threadIdx.x; i < STATE * H; i += blockDim.x) sW1[i] = W1[i];
    for (int i = threadIdx.x; i < H * H; i += blockDim.x)     sW2[i] = W2[i];
    if (threadIdx.x < H)  sW3[threadIdx.x] = W3[threadIdx.x];
    if (threadIdx.x == 0) sb3[0] = b3[0];

    const long long rowEnd    = (long long)row0 + nrows;
    const long long blockRow0 = (long long)row0 + (long long)blockIdx.x * K2_ROWS;
    const float* __restrict__ nsc_g = out + 3LL * B;

    // Coalesced stage of up to 256 contiguous nsc rows.
    if (blockRow0 + K2_ROWS <= rowEnd) {
        const float4* __restrict__ src =
            reinterpret_cast<const float4*>(nsc_g + blockRow0 * STATE);
        float4* __restrict__ dst = reinterpret_cast<float4*>(s_nsc);
        #pragma unroll 4
        for (int i = threadIdx.x; i < K2_ROWS * STATE / 4; i += K2_THREADS)
            dst[i] = __ldg(&src[i]);
    } else {
        for (int i = threadIdx.x; i < K2_ROWS * STATE; i += K2_THREADS) {
            const long long g = blockRow0 * STATE + i;
            if (g < rowEnd * STATE) s_nsc[i] = nsc_g[g];
        }
    }
    __syncthreads();

    const long long b = blockRow0 + threadIdx.x;
    if (b >= rowEnd) return;

    const float* __restrict__ myn = s_nsc + threadIdx.x * STATE;

    unsigned long long h1p[H / 2];
    #pragma unroll
    for (int j = 0; j < H / 2; j++) h1p[j] = 0ULL;

    #pragma unroll 3
    for (int d = 0; d < STATE; d++) {
        const unsigned long long vd = pack2(myn[d]);
        const ulonglong2* __restrict__ w1p =
            reinterpret_cast<const ulonglong2*>(&sW1[d * H]);
        #pragma unroll
        for (int q = 0; q < H / 4; q++) {
            ulonglong2 w = w1p[q];
            ffma2(h1p[q * 2 + 0], vd, w.x);
            ffma2(h1p[q * 2 + 1], vd, w.y);
        }
    }

    float h1[H];
    #pragma unroll
    for (int j = 0; j < H / 2; j++) {
        float lo, hi;
        unpack2(h1p[j], lo, hi);
        h1[2 * j + 0] = fmaxf(lo, 0.0f);
        h1[2 * j + 1] = fmaxf(hi, 0.0f);
    }

    unsigned long long h2p[H / 2];
    #pragma unroll
    for (int j = 0; j < H / 2; j++) h2p[j] = 0ULL;
    #pragma unroll
    for (int i = 0; i < H; i++) {
        const unsigned long long vi = pack2(h1[i]);
        const ulonglong2* __restrict__ w2p =
            reinterpret_cast<const ulonglong2*>(&sW2[i * H]);
        #pragma unroll
        for (int q = 0; q < H / 4; q++) {
            ulonglong2 w = w2p[q];
            ffma2(h2p[q * 2 + 0], vi, w.x);
            ffma2(h2p[q * 2 + 1], vi, w.y);
        }
    }

    float ret = sb3[0];
    #pragma unroll
    for (int j = 0; j < H / 2; j++) {
        float lo, hi;
        unpack2(h2p[j], lo, hi);
        ret = fmaf(fmaxf(lo, 0.0f), sW3[2 * j + 0], ret);
        ret = fmaf(fmaxf(hi, 0.0f), sW3[2 * j + 1], ret);
    }

    const float imm = out[(long long)B + b];
    out[b]                      = imm + ret;  // symbolic_val
    out[2LL * (long long)B + b] = ret;        // next_return
}

static const int K2_SMEM_BYTES =
    (K2_ROWS * STATE + STATE * H + H * H + H + 1) * (int)sizeof(float);

// Persistent stream/events: created once on the first (non-captured) call;
// thereafter they are fixed resources referenced identically on every call,
// so the captured work is deterministic and identical each launch.
static cudaStream_t g_s2 = nullptr;
static cudaEvent_t  g_ev1[NCHUNK];
static cudaEvent_t  g_evJoin = nullptr;

extern "C" void kernel_launch(void* const* d_in, const int* in_sizes, int n_in,
                              void* d_out, int out_size) {
    const float* obs = (const float*)d_in[0];
    const float* action_count = (const float*)d_in[1];
    const float* W1 = (const float*)d_in[2];
    const float* W2 = (const float*)d_in[3];
    const float* W3 = (const float*)d_in[4];
    const float* b3 = (const float*)d_in[5];
    float* out = (float*)d_out;

    const int B = in_sizes[0] / (3 * STATE);

    if (g_s2 == nullptr) {
        cudaStreamCreateWithFlags(&g_s2, cudaStreamNonBlocking);
        for (int i = 0; i < NCHUNK; i++)
            cudaEventCreateWithFlags(&g_ev1[i], cudaEventDisableTiming);
        cudaEventCreateWithFlags(&g_evJoin, cudaEventDisableTiming);
    }

    cudaFuncSetAttribute(k2_mlp, cudaFuncAttributeMaxDynamicSharedMemorySize,
                         K2_SMEM_BYTES);

    // Producer chain on the capture-origin (legacy) stream.
    for (int c = 0; c < NCHUNK; c++) {
        const int r0 = (int)((long long)B * c / NCHUNK);
        const int r1 = (int)((long long)B * (c + 1) / NCHUNK);
        const int n  = r1 - r0;
        const int blocks1 = (n + WARPS_K1 - 1) / WARPS_K1;
        k1_nsc_reward<<<blocks1, 32 * WARPS_K1, 0, 0>>>(
            obs, action_count, out, B, r0, n);
        cudaEventRecord(g_ev1[c], 0);
    }

    // Consumer chain on stream 2, forked per-chunk from the producer chain.
    for (int c = 0; c < NCHUNK; c++) {
        const int r0 = (int)((long long)B * c / NCHUNK);
        const int r1 = (int)((long long)B * (c + 1) / NCHUNK);
        const int n  = r1 - r0;
        cudaStreamWaitEvent(g_s2, g_ev1[c], 0);
        const int blocks2 = (n + K2_ROWS - 1) / K2_ROWS;
        k2_mlp<<<blocks2, K2_THREADS, K2_SMEM_BYTES, g_s2>>>(
            W1, W2, W3, b3, out, B, r0, n);
    }

    // Join stream 2 back into the capture-origin stream.
    cudaEventRecord(g_evJoin, g_s2);
    cudaStreamWaitEvent(0, g_evJoin, 0);
}

// round 12
// speedup vs baseline: 1.6208x; 1.6208x over previous
#include <cuda_runtime.h>
#include <cuda_bf16.h>

#define SIDE 9
#define STATE 81
#define NA 5
#define ROWLEN 405
#define H 32
#define RPB1 8           // K1 rows per block
#define K2_THREADS 256
#define K2_ROWS 256

// ---------------------------------------------------------------------------
// K1 v2: block stages 8 contiguous ac rows via float4, warp-per-row gather,
// block-wide float4 store of the contiguous nsc slab.
// ---------------------------------------------------------------------------
__global__ __launch_bounds__(256) void k1_nsc_reward(
    const float* __restrict__ obs,          // (B, 3*STATE)
    const float* __restrict__ acr_g,        // (B, STATE*NA)
    float* __restrict__ out,                // [sym(B), imm(B), ret(B), nsc(B*81)]
    int B)
{
    __shared__ float s_ac[RPB1 * ROWLEN];    // 12.96 KB
    __shared__ float s_nsc[RPB1 * STATE];    //  2.6 KB

    const int tid  = threadIdx.x;
    const int wid  = tid >> 5;
    const int lane = tid & 31;
    const long long row0 = (long long)blockIdx.x * RPB1;
    const bool full = (row0 + RPB1 <= B);

    // ---- Stage 8 rows of action_count (3240 floats, 16B aligned) ----
    if (full) {
        const float4* __restrict__ src =
            reinterpret_cast<const float4*>(acr_g + row0 * ROWLEN);
        float4* __restrict__ dst = reinterpret_cast<float4*>(s_ac);
        #pragma unroll
        for (int i = tid; i < RPB1 * ROWLEN / 4; i += 256)
            dst[i] = __ldg(&src[i]);
    } else {
        for (int i = tid; i < RPB1 * ROWLEN; i += 256) {
            const long long g = row0 * ROWLEN + i;
            if (g < (long long)B * ROWLEN) s_ac[i] = acr_g[g];
        }
    }
    __syncthreads();

    // ---- Warp-per-row gather + reward ----
    const long long row = row0 + wid;
    if (row < B) {
        const float* __restrict__ sp = s_ac + wid * ROWLEN;
        const float* __restrict__ dem = obs + row * (3 * STATE) + 2 * STATE;
        float* __restrict__ nrow = s_nsc + wid * STATE;

        float imm = 0.0f;
        #pragma unroll
        for (int k = 0; k < 3; k++) {
            const int c = lane + 32 * k;
            if (c < STATE) {
                const int r   = c / SIDE;
                const int col = c - r * SIDE;
                float v = sp[c * NA + 0];
                if (r == 0)        v += sp[c * NA + 1];
                if (r < SIDE - 1)  v += sp[(c + SIDE) * NA + 1];
                if (r == SIDE - 1) v += sp[c * NA + 2];
                if (r > 0)         v += sp[(c - SIDE) * NA + 2];
                if (col == 0)      v += sp[c * NA + 3];
                if (col < SIDE - 1)v += sp[(c + 1) * NA + 3];
                if (col == SIDE-1) v += sp[c * NA + 4];
                if (col > 0)       v += sp[(c - 1) * NA + 4];

                nrow[c] = v;
                imm += fminf(v, __ldg(&dem[c]));
            }
        }

        #pragma unroll
        for (int o = 16; o; o >>= 1) imm += __shfl_xor_sync(0xffffffffu, imm, o);
        if (lane == 0) out[(long long)B + row] = imm;
    }
    __syncthreads();

    // ---- Block-wide float4 store of the contiguous nsc slab (648 floats) ----
    if (full) {
        const float4* __restrict__ src = reinterpret_cast<const float4*>(s_nsc);
        float4* __restrict__ dst =
            reinterpret_cast<float4*>(out + 3LL * B + row0 * STATE);
        if (tid < RPB1 * STATE / 4) dst[tid] = src[tid];
    } else {
        for (int i = tid; i < RPB1 * STATE; i += 256) {
            const long long g = row0 * STATE + i;
            if (g < (long long)B * STATE) out[3LL * B + g] = s_nsc[i];
        }
    }
}

// ---------------------------------------------------------------------------
// Packed f32x2 helpers (sm_103a FFMA2)
// ---------------------------------------------------------------------------
__device__ __forceinline__ unsigned long long pack2(float x) {
    unsigned long long r;
    asm("mov.b64 %0, {%1, %1};" : "=l"(r) : "f"(x));
    return r;
}
__device__ __forceinline__ void ffma2(unsigned long long& d,
                                      unsigned long long a,
                                      unsigned long long b) {
    asm("fma.rn.f32x2 %0, %1, %2, %0;" : "+l"(d) : "l"(a), "l"(b));
}
__device__ __forceinline__ void unpack2(unsigned long long p, float& lo, float& hi) {
    asm("mov.b64 {%0, %1}, %2;" : "=f"(lo), "=f"(hi) : "l"(p));
}

// ---------------------------------------------------------------------------
// K2: round-3 proven form (thread-per-row, block-staged nsc, FFMA2).
// ---------------------------------------------------------------------------
__global__ __launch_bounds__(K2_THREADS) void k2_mlp(
    const float* __restrict__ W1,
    const float* __restrict__ W2,
    const float* __restrict__ W3,
    const float* __restrict__ b3,
    float* __restrict__ out,
    int B)
{
    extern __shared__ float smem[];
    float* s_nsc = smem;                          // K2_ROWS * STATE
    float* sW1   = s_nsc + K2_ROWS * STATE;       // STATE * H
    float* sW2   = sW1 + STATE * H;               // H * H
    float* sW3   = sW2 + H * H;                   // H
    float* sb3   = sW3 + H;                       // 1

    for (int i = threadIdx.x; i < STATE * H; i += blockDim.x) sW1[i] = W1[i];
    for (int i = threadIdx.x; i < H * H; i += blockDim.x)     sW2[i] = W2[i];
    if (threadIdx.x < H)  sW3[threadIdx.x] = W3[threadIdx.x];
    if (threadIdx.x == 0) sb3[0] = b3[0];

    const long long blockRow0 = (long long)blockIdx.x * K2_ROWS;
    const float* __restrict__ nsc_g = out + 3LL * B;

    if (blockRow0 + K2_ROWS <= B) {
        const float4* __restrict__ src =
            reinterpret_cast<const float4*>(nsc_g + blockRow0 * STATE);
        float4* __restrict__ dst = reinterpret_cast<float4*>(s_nsc);
        #pragma unroll 4
        for (int i = threadIdx.x; i < K2_ROWS * STATE / 4; i += K2_THREADS)
            dst[i] = __ldg(&src[i]);
    } else {
        for (int i = threadIdx.x; i < K2_ROWS * STATE; i += K2_THREADS) {
            const long long g = blockRow0 * STATE + i;
            if (g < (long long)B * STATE) s_nsc[i] = nsc_g[g];
        }
    }
    __syncthreads();

    const long long b = blockRow0 + threadIdx.x;
    if (b >= B) return;

    const float* __restrict__ myn = s_nsc + threadIdx.x * STATE;

    unsigned long long h1p[H / 2];
    #pragma unroll
    for (int j = 0; j < H / 2; j++) h1p[j] = 0ULL;

    #pragma unroll 3
    for (int d = 0; d < STATE; d++) {
        const unsigned long long vd = pack2(myn[d]);
        const ulonglong2* __restrict__ w1p =
            reinterpret_cast<const ulonglong2*>(&sW1[d * H]);
        #pragma unroll
        for (int q = 0; q < H / 4; q++) {
            ulonglong2 w = w1p[q];
            ffma2(h1p[q * 2 + 0], vd, w.x);
            ffma2(h1p[q * 2 + 1], vd, w.y);
        }
    }

    float h1[H];
    #pragma unroll
    for (int j = 0; j < H / 2; j++) {
        float lo, hi;
        unpack2(h1p[j], lo, hi);
        h1[2 * j + 0] = fmaxf(lo, 0.0f);
        h1[2 * j + 1] = fmaxf(hi, 0.0f);
    }

    unsigned long long h2p[H / 2];
    #pragma unroll
    for (int j = 0; j < H / 2; j++) h2p[j] = 0ULL;
    #pragma unroll
    for (int i = 0; i < H; i++) {
        const unsigned long long vi = pack2(h1[i]);
        const ulonglong2* __restrict__ w2p =
            reinterpret_cast<const ulonglong2*>(&sW2[i * H]);
        #pragma unroll
        for (int q = 0; q < H / 4; q++) {
            ulonglong2 w = w2p[q];
            ffma2(h2p[q * 2 + 0], vi, w.x);
            ffma2(h2p[q * 2 + 1], vi, w.y);
        }
    }

    float ret = sb3[0];
    #pragma unroll
    for (int j = 0; j < H / 2; j++) {
        float lo, hi;
        unpack2(h2p[j], lo, hi);
        ret = fmaf(fmaxf(lo, 0.0f), sW3[2 * j + 0], ret);
        ret = fmaf(fmaxf(hi, 0.0f), sW3[2 * j + 1], ret);
    }

    const float imm = out[(long long)B + b];
    out[b]                      = imm + ret;  // symbolic_val
    out[2LL * (long long)B + b] = ret;        // next_return
}

static const int K2_SMEM_BYTES =
    (K2_ROWS * STATE + STATE * H + H * H + H + 1) * (int)sizeof(float);

extern "C" void kernel_launch(void* const* d_in, const int* in_sizes, int n_in,
                              void* d_out, int out_size) {
    const float* obs = (const float*)d_in[0];
    const float* action_count = (const float*)d_in[1];
    const float* W1 = (const float*)d_in[2];
    const float* W2 = (const float*)d_in[3];
    const float* W3 = (const float*)d_in[4];
    const float* b3 = (const float*)d_in[5];
    float* out = (float*)d_out;

    const int B = in_sizes[0] / (3 * STATE);

    cudaFuncSetAttribute(k2_mlp, cudaFuncAttributeMaxDynamicSharedMemorySize,
                         K2_SMEM_BYTES);

    const int blocks1 = (B + RPB1 - 1) / RPB1;
    k1_nsc_reward<<<blocks1, 256>>>(obs, action_count, out, B);

    const int blocks2 = (B + K2_ROWS - 1) / K2_ROWS;
    k2_mlp<<<blocks2, K2_THREADS, K2_SMEM_BYTES>>>(W1, W2, W3, b3, out, B);
}